// round 6
// baseline (speedup 1.0000x reference)
#include <cuda_runtime.h>

#define BB  2
#define SS  2048
#define DDIM 1024
#define HH  16
#define HDD 64

// Scratch (allocation-free rule: __device__ globals)
__device__ float g_q[(size_t)BB*HH*SS*HDD];   // [B,H,S,HD]
__device__ float g_k[(size_t)BB*HH*SS*HDD];
__device__ float g_v[(size_t)BB*HH*SS*HDD];
__device__ float g_att[(size_t)BB*SS*DDIM];   // [B,S,D] attention output

// ---------------------------------------------------------------------------
// C[M,N] = X[M,K] @ W[N,K]^T + bias     (K = DDIM = 1024)
// 64x64 tile, 256 threads, 4x4 per thread. If HEAD_MAJOR, scatter the output
// into [B,H,S,HD] layout for the attention kernel.
// ---------------------------------------------------------------------------
template<bool HEAD_MAJOR>
__global__ void __launch_bounds__(256) gemm_bias_kernel(
    const float* __restrict__ X, const float* __restrict__ W,
    const float* __restrict__ bias, float* __restrict__ C)
{
    __shared__ float Xs[16][65];   // [k][m], pad 65 -> conflict-free reads
    __shared__ float Ws[16][65];   // [k][n]

    const int tid = threadIdx.x;
    const int tx  = tid & 15;
    const int ty  = tid >> 4;
    const int m0  = blockIdx.y * 64;
    const int n0  = blockIdx.x * 64;
    const int lrow = tid >> 2;        // 0..63
    const int lk   = (tid & 3) * 4;   // 0,4,8,12

    float acc[4][4] = {};

    for (int k0 = 0; k0 < DDIM; k0 += 16) {
        float4 xv = *(const float4*)(X + (size_t)(m0 + lrow) * DDIM + k0 + lk);
        float4 wv = *(const float4*)(W + (size_t)(n0 + lrow) * DDIM + k0 + lk);
        Xs[lk+0][lrow] = xv.x; Xs[lk+1][lrow] = xv.y;
        Xs[lk+2][lrow] = xv.z; Xs[lk+3][lrow] = xv.w;
        Ws[lk+0][lrow] = wv.x; Ws[lk+1][lrow] = wv.y;
        Ws[lk+2][lrow] = wv.z; Ws[lk+3][lrow] = wv.w;
        __syncthreads();
        #pragma unroll
        for (int k = 0; k < 16; k++) {
            float a[4], b[4];
            #pragma unroll
            for (int i = 0; i < 4; i++) a[i] = Xs[k][ty*4+i];
            #pragma unroll
            for (int j = 0; j < 4; j++) b[j] = Ws[k][tx*4+j];
            #pragma unroll
            for (int i = 0; i < 4; i++)
                #pragma unroll
                for (int j = 0; j < 4; j++)
                    acc[i][j] = fmaf(a[i], b[j], acc[i][j]);
        }
        __syncthreads();
    }

    #pragma unroll
    for (int i = 0; i < 4; i++) {
        const int m = m0 + ty*4 + i;
        #pragma unroll
        for (int j = 0; j < 4; j++) {
            const int n = n0 + tx*4 + j;
            const float v = acc[i][j] + bias[n];
            if (HEAD_MAJOR) {
                const int b = m / SS, s = m % SS;
                const int h = n / HDD, d = n % HDD;
                C[(((size_t)(b*HH + h))*SS + s)*HDD + d] = v;
            } else {
                C[(size_t)m*DDIM + n] = v;
            }
        }
    }
}

// ---------------------------------------------------------------------------
// Flash-attention (fp32, streaming softmax).
// grid = (S/64, H, B); block = 256 threads.
// Q tile 64x64 resident; loop over key tiles of 32.
// Output written directly in [B,S,D] layout (so O-projection is a plain GEMM).
// ---------------------------------------------------------------------------
__global__ void __launch_bounds__(256) attention_kernel(
    const int* __restrict__ mask, float* __restrict__ O)
{
    const int qt = blockIdx.x;
    const int h  = blockIdx.y;
    const int b  = blockIdx.z;

    const float* __restrict__ Qg = g_q + ((size_t)(b*HH + h))*SS*HDD;
    const float* __restrict__ Kg = g_k + ((size_t)(b*HH + h))*SS*HDD;
    const float* __restrict__ Vg = g_v + ((size_t)(b*HH + h))*SS*HDD;

    __shared__ float Qs[64][65];  // 16.6 KB
    __shared__ float Ks[32][65];  //  8.3 KB
    __shared__ float Vs[32][65];  //  8.3 KB
    __shared__ float Ps[64][33];  //  8.4 KB   (total 41.7 KB < 48 KB static)

    const int tid = threadIdx.x;
    const int tx  = tid & 15;
    const int ty  = tid >> 4;

    // Load Q tile (64 rows x 64 cols)
    for (int i = tid; i < 64*16; i += 256) {
        const int r = i >> 4, c = (i & 15) * 4;
        float4 v = *(const float4*)(Qg + (size_t)(qt*64 + r)*HDD + c);
        Qs[r][c+0] = v.x; Qs[r][c+1] = v.y; Qs[r][c+2] = v.z; Qs[r][c+3] = v.w;
    }

    float m_run[4], l_run[4], acc[4][4];
    #pragma unroll
    for (int i = 0; i < 4; i++) {
        m_run[i] = -1e30f; l_run[i] = 0.f;
        #pragma unroll
        for (int j = 0; j < 4; j++) acc[i][j] = 0.f;
    }

    for (int kt = 0; kt < SS/32; kt++) {
        // Load K,V tiles (32 x 64 each)
        for (int i = tid; i < 32*16; i += 256) {
            const int r = i >> 4, c = (i & 15) * 4;
            float4 kv = *(const float4*)(Kg + (size_t)(kt*32 + r)*HDD + c);
            float4 vv = *(const float4*)(Vg + (size_t)(kt*32 + r)*HDD + c);
            Ks[r][c+0] = kv.x; Ks[r][c+1] = kv.y; Ks[r][c+2] = kv.z; Ks[r][c+3] = kv.w;
            Vs[r][c+0] = vv.x; Vs[r][c+1] = vv.y; Vs[r][c+2] = vv.z; Vs[r][c+3] = vv.w;
        }
        __syncthreads();

        // S = Q K^T  (64x32, 4 rows x 2 cols per thread)
        float s[4][2] = {};
        #pragma unroll 8
        for (int d = 0; d < 64; d++) {
            float a[4], kk[2];
            #pragma unroll
            for (int i = 0; i < 4; i++) a[i] = Qs[ty*4+i][d];
            #pragma unroll
            for (int j = 0; j < 2; j++) kk[j] = Ks[tx*2+j][d];
            #pragma unroll
            for (int i = 0; i < 4; i++)
                #pragma unroll
                for (int j = 0; j < 2; j++)
                    s[i][j] = fmaf(a[i], kk[j], s[i][j]);
        }

        // scale + mask (mask applied AFTER scaling, matching reference)
        const int mk0 = mask[b*SS + kt*32 + tx*2 + 0];
        const int mk1 = mask[b*SS + kt*32 + tx*2 + 1];
        #pragma unroll
        for (int i = 0; i < 4; i++) {
            s[i][0] = (mk0 == 0) ? -1e9f : s[i][0] * 0.125f;
            s[i][1] = (mk1 == 0) ? -1e9f : s[i][1] * 0.125f;
        }

        // row max across the 16 lanes owning each row
        float mt[4];
        #pragma unroll
        for (int i = 0; i < 4; i++) mt[i] = fmaxf(s[i][0], s[i][1]);
        #pragma unroll
        for (int off = 1; off < 16; off <<= 1)
            #pragma unroll
            for (int i = 0; i < 4; i++)
                mt[i] = fmaxf(mt[i], __shfl_xor_sync(0xffffffffu, mt[i], off));

        float m_new[4], corr[4];
        #pragma unroll
        for (int i = 0; i < 4; i++) {
            m_new[i] = fmaxf(m_run[i], mt[i]);
            corr[i]  = __expf(m_run[i] - m_new[i]);
            m_run[i] = m_new[i];
        }

        float p[4][2], rs[4];
        #pragma unroll
        for (int i = 0; i < 4; i++) {
            p[i][0] = __expf(s[i][0] - m_new[i]);
            p[i][1] = __expf(s[i][1] - m_new[i]);
            rs[i]   = p[i][0] + p[i][1];
        }
        #pragma unroll
        for (int off = 1; off < 16; off <<= 1)
            #pragma unroll
            for (int i = 0; i < 4; i++)
                rs[i] += __shfl_xor_sync(0xffffffffu, rs[i], off);

        #pragma unroll
        for (int i = 0; i < 4; i++) {
            l_run[i] = l_run[i] * corr[i] + rs[i];
            #pragma unroll
            for (int j = 0; j < 4; j++) acc[i][j] *= corr[i];
        }

        // stash P and do acc += P V
        #pragma unroll
        for (int i = 0; i < 4; i++) {
            Ps[ty*4+i][tx*2+0] = p[i][0];
            Ps[ty*4+i][tx*2+1] = p[i][1];
        }
        __syncthreads();

        #pragma unroll 8
        for (int k = 0; k < 32; k++) {
            float a2[4], b2[4];
            #pragma unroll
            for (int i = 0; i < 4; i++) a2[i] = Ps[ty*4+i][k];
            #pragma unroll
            for (int j = 0; j < 4; j++) b2[j] = Vs[k][tx*4+j];
            #pragma unroll
            for (int i = 0; i < 4; i++)
                #pragma unroll
                for (int j = 0; j < 4; j++)
                    acc[i][j] = fmaf(a2[i], b2[j], acc[i][j]);
        }
        __syncthreads();
    }

    // epilogue: normalize and write [B,S,D] layout
    #pragma unroll
    for (int i = 0; i < 4; i++) {
        const float inv = 1.f / l_run[i];
        const int r = qt*64 + ty*4 + i;
        float4 o4 = make_float4(acc[i][0]*inv, acc[i][1]*inv,
                                acc[i][2]*inv, acc[i][3]*inv);
        *(float4*)(O + ((size_t)(b*SS + r))*DDIM + h*HDD + tx*4) = o4;
    }
}

// ---------------------------------------------------------------------------
extern "C" void kernel_launch(void* const* d_in, const int* in_sizes, int n_in,
                              void* d_out, int out_size)
{
    const float* x    = (const float*)d_in[0];
    const int*   mask = (const int*)  d_in[1];
    const float* Wq   = (const float*)d_in[2];
    const float* bq   = (const float*)d_in[3];
    const float* Wk   = (const float*)d_in[4];
    const float* bk   = (const float*)d_in[5];
    const float* Wv   = (const float*)d_in[6];
    const float* bv   = (const float*)d_in[7];
    const float* Wo   = (const float*)d_in[8];
    const float* bo   = (const float*)d_in[9];
    float* out = (float*)d_out;

    float *q, *k, *v, *att;
    cudaGetSymbolAddress((void**)&q,   g_q);
    cudaGetSymbolAddress((void**)&k,   g_k);
    cudaGetSymbolAddress((void**)&v,   g_v);
    cudaGetSymbolAddress((void**)&att, g_att);

    const dim3 gGemm(DDIM/64, (BB*SS)/64);   // (16, 64)
    gemm_bias_kernel<true><<<gGemm, 256>>>(x, Wq, bq, q);
    gemm_bias_kernel<true><<<gGemm, 256>>>(x, Wk, bk, k);
    gemm_bias_kernel<true><<<gGemm, 256>>>(x, Wv, bv, v);

    const dim3 gAttn(SS/64, HH, BB);         // (32, 16, 2)
    attention_kernel<<<gAttn, 256>>>(mask, att);

    gemm_bias_kernel<false><<<gGemm, 256>>>(att, Wo, bo, out);
}

// round 7
// speedup vs baseline: 3.4450x; 3.4450x over previous
#include <cuda_runtime.h>

#define BB   2
#define SS   2048
#define DDIM 1024
#define HH   16
#define HDD  64

// Scratch (allocation-free rule: __device__ globals)
__device__ float g_q[(size_t)BB*HH*SS*HDD];   // [B,H,S,HD]
__device__ float g_k[(size_t)BB*HH*SS*HDD];
__device__ float g_v[(size_t)BB*HH*SS*HDD];
__device__ float g_att[(size_t)BB*SS*DDIM];   // [B,S,D]

// ---------------------------------------------------------------------------
// helpers
// ---------------------------------------------------------------------------
__device__ __forceinline__ unsigned f2tf32(float x) {
    unsigned r;
    asm("cvt.rna.tf32.f32 %0, %1;" : "=r"(r) : "f"(x));
    return r;
}

// D += A*B, m16n8k8 tf32
__device__ __forceinline__ void mma_tf32(float* c, const unsigned* a,
                                         unsigned b0, unsigned b1) {
    asm volatile(
        "mma.sync.aligned.m16n8k8.row.col.f32.tf32.tf32.f32 "
        "{%0,%1,%2,%3}, {%4,%5,%6,%7}, {%8,%9}, {%0,%1,%2,%3};\n"
        : "+f"(c[0]), "+f"(c[1]), "+f"(c[2]), "+f"(c[3])
        : "r"(a[0]), "r"(a[1]), "r"(a[2]), "r"(a[3]), "r"(b0), "r"(b1));
}

// ---------------------------------------------------------------------------
// TF32 GEMM: C[M,N] = X[M,K] @ W[N,K]^T + bias,  M=4096, N=K=1024.
// Block 256 thr (8 warps), tile 128x128, k-slab 16, double-buffered smem.
// Warp grid 2(m) x 4(n): warp tile 64x32.
// ---------------------------------------------------------------------------
#define GPAD 20   // smem row stride (floats): g*20+t distinct mod 32 -> conflict-free

template<bool HEAD_MAJOR>
__global__ void __launch_bounds__(256) gemm_tf32_kernel(
    const float* __restrict__ X, const float* __restrict__ W,
    const float* __restrict__ bias, float* __restrict__ C)
{
    __shared__ unsigned As[2][128*GPAD];
    __shared__ unsigned Bs[2][128*GPAD];

    const int tid  = threadIdx.x;
    const int warp = tid >> 5;
    const int lane = tid & 31;
    const int g    = lane >> 2;
    const int t    = lane & 3;
    const int wm   = (warp >> 2) * 64;   // warp m offset in block tile
    const int wn   = (warp & 3) * 32;    // warp n offset
    const int m0   = blockIdx.y * 128;
    const int n0   = blockIdx.x * 128;

    const int lr = tid >> 2;           // 0..63
    const int lc = (tid & 3) * 4;      // 0,4,8,12

    float acc[4][4][4];
    #pragma unroll
    for (int mi = 0; mi < 4; mi++)
        #pragma unroll
        for (int nj = 0; nj < 4; nj++)
            #pragma unroll
            for (int r = 0; r < 4; r++) acc[mi][nj][r] = 0.f;

    // preload slab 0
    float4 ax0 = *(const float4*)(X + (size_t)(m0 + lr)      * DDIM + lc);
    float4 ax1 = *(const float4*)(X + (size_t)(m0 + lr + 64) * DDIM + lc);
    float4 bx0 = *(const float4*)(W + (size_t)(n0 + lr)      * DDIM + lc);
    float4 bx1 = *(const float4*)(W + (size_t)(n0 + lr + 64) * DDIM + lc);
    {
        unsigned* a = As[0]; unsigned* bsh = Bs[0];
        a[lr*GPAD + lc+0] = f2tf32(ax0.x); a[lr*GPAD + lc+1] = f2tf32(ax0.y);
        a[lr*GPAD + lc+2] = f2tf32(ax0.z); a[lr*GPAD + lc+3] = f2tf32(ax0.w);
        a[(lr+64)*GPAD + lc+0] = f2tf32(ax1.x); a[(lr+64)*GPAD + lc+1] = f2tf32(ax1.y);
        a[(lr+64)*GPAD + lc+2] = f2tf32(ax1.z); a[(lr+64)*GPAD + lc+3] = f2tf32(ax1.w);
        bsh[lr*GPAD + lc+0] = f2tf32(bx0.x); bsh[lr*GPAD + lc+1] = f2tf32(bx0.y);
        bsh[lr*GPAD + lc+2] = f2tf32(bx0.z); bsh[lr*GPAD + lc+3] = f2tf32(bx0.w);
        bsh[(lr+64)*GPAD + lc+0] = f2tf32(bx1.x); bsh[(lr+64)*GPAD + lc+1] = f2tf32(bx1.y);
        bsh[(lr+64)*GPAD + lc+2] = f2tf32(bx1.z); bsh[(lr+64)*GPAD + lc+3] = f2tf32(bx1.w);
    }
    __syncthreads();

    int buf = 0;
    for (int ks = 0; ks < DDIM/16; ks++) {
        if (ks < DDIM/16 - 1) {
            const int kn = (ks + 1) * 16;
            ax0 = *(const float4*)(X + (size_t)(m0 + lr)      * DDIM + kn + lc);
            ax1 = *(const float4*)(X + (size_t)(m0 + lr + 64) * DDIM + kn + lc);
            bx0 = *(const float4*)(W + (size_t)(n0 + lr)      * DDIM + kn + lc);
            bx1 = *(const float4*)(W + (size_t)(n0 + lr + 64) * DDIM + kn + lc);
        }

        const unsigned* a_s = As[buf];
        const unsigned* b_s = Bs[buf];
        #pragma unroll
        for (int kk = 0; kk < 16; kk += 8) {
            unsigned afr[4][4];
            #pragma unroll
            for (int mi = 0; mi < 4; mi++) {
                const int r = wm + 16*mi + g;
                afr[mi][0] = a_s[r*GPAD     + kk + t];
                afr[mi][1] = a_s[(r+8)*GPAD + kk + t];
                afr[mi][2] = a_s[r*GPAD     + kk + t + 4];
                afr[mi][3] = a_s[(r+8)*GPAD + kk + t + 4];
            }
            #pragma unroll
            for (int nj = 0; nj < 4; nj++) {
                const int rn = wn + 8*nj + g;
                const unsigned b0 = b_s[rn*GPAD + kk + t];
                const unsigned b1 = b_s[rn*GPAD + kk + t + 4];
                #pragma unroll
                for (int mi = 0; mi < 4; mi++)
                    mma_tf32(acc[mi][nj], afr[mi], b0, b1);
            }
        }

        if (ks < DDIM/16 - 1) {
            unsigned* a = As[buf ^ 1]; unsigned* bsh = Bs[buf ^ 1];
            a[lr*GPAD + lc+0] = f2tf32(ax0.x); a[lr*GPAD + lc+1] = f2tf32(ax0.y);
            a[lr*GPAD + lc+2] = f2tf32(ax0.z); a[lr*GPAD + lc+3] = f2tf32(ax0.w);
            a[(lr+64)*GPAD + lc+0] = f2tf32(ax1.x); a[(lr+64)*GPAD + lc+1] = f2tf32(ax1.y);
            a[(lr+64)*GPAD + lc+2] = f2tf32(ax1.z); a[(lr+64)*GPAD + lc+3] = f2tf32(ax1.w);
            bsh[lr*GPAD + lc+0] = f2tf32(bx0.x); bsh[lr*GPAD + lc+1] = f2tf32(bx0.y);
            bsh[lr*GPAD + lc+2] = f2tf32(bx0.z); bsh[lr*GPAD + lc+3] = f2tf32(bx0.w);
            bsh[(lr+64)*GPAD + lc+0] = f2tf32(bx1.x); bsh[(lr+64)*GPAD + lc+1] = f2tf32(bx1.y);
            bsh[(lr+64)*GPAD + lc+2] = f2tf32(bx1.z); bsh[(lr+64)*GPAD + lc+3] = f2tf32(bx1.w);
        }
        __syncthreads();
        buf ^= 1;
    }

    // epilogue: bias + store (optionally scatter to head-major [B,H,S,HD])
    #pragma unroll
    for (int mi = 0; mi < 4; mi++) {
        const int mA = m0 + wm + 16*mi + g;
        #pragma unroll
        for (int nj = 0; nj < 4; nj++) {
            const int n = n0 + wn + 8*nj + 2*t;
            const float b0 = bias[n], b1 = bias[n+1];
            float2 v0 = make_float2(acc[mi][nj][0] + b0, acc[mi][nj][1] + b1);
            float2 v1 = make_float2(acc[mi][nj][2] + b0, acc[mi][nj][3] + b1);
            if (HEAD_MAJOR) {
                const int h = n >> 6, d = n & 63;
                const int bb0 = mA >> 11, s0 = mA & 2047;
                *(float2*)(C + (((size_t)(bb0*HH + h))*SS + s0)*HDD + d) = v0;
                const int mB = mA + 8;
                const int bb1 = mB >> 11, s1 = mB & 2047;
                *(float2*)(C + (((size_t)(bb1*HH + h))*SS + s1)*HDD + d) = v1;
            } else {
                *(float2*)(C + (size_t)mA*DDIM + n)     = v0;
                *(float2*)(C + (size_t)(mA+8)*DDIM + n) = v1;
            }
        }
    }
}

// ---------------------------------------------------------------------------
// TF32 flash attention. Block = 128 thr (4 warps), Q tile 64 rows (16/warp),
// key tile 64. Dynamic smem: Ks[64*68] + Vs[64*68] + Ps[64*68] tf32 words.
// Ps doubles as the Q staging buffer before the main loop.
// ---------------------------------------------------------------------------
#define APAD 68   // 68 mod 32 = 4 -> frag reads (4g+t) conflict-free

__global__ void __launch_bounds__(128) attention_tf32_kernel(
    const int* __restrict__ mask, float* __restrict__ O)
{
    extern __shared__ unsigned sm[];
    unsigned* Ks = sm;
    unsigned* Vs = sm + 64*APAD;
    unsigned* Ps = sm + 2*64*APAD;

    const int qt = blockIdx.x;
    const int h  = blockIdx.y;
    const int b  = blockIdx.z;

    const float* __restrict__ Qg = g_q + ((size_t)(b*HH + h))*SS*HDD + (size_t)qt*64*HDD;
    const float* __restrict__ Kg = g_k + ((size_t)(b*HH + h))*SS*HDD;
    const float* __restrict__ Vg = g_v + ((size_t)(b*HH + h))*SS*HDD;

    const int tid  = threadIdx.x;
    const int warp = tid >> 5;
    const int lane = tid & 31;
    const int g    = lane >> 2;
    const int t    = lane & 3;
    const int mrow = warp * 16;

    // stage Q (64x64) into Ps, then pull A-fragments into registers
    for (int i = tid; i < 64*16; i += 128) {
        const int r = i >> 4, c = (i & 15) * 4;
        float4 v = *(const float4*)(Qg + (size_t)r*HDD + c);
        Ps[r*APAD + c+0] = f2tf32(v.x); Ps[r*APAD + c+1] = f2tf32(v.y);
        Ps[r*APAD + c+2] = f2tf32(v.z); Ps[r*APAD + c+3] = f2tf32(v.w);
    }
    __syncthreads();

    unsigned qa[8][4];
    #pragma unroll
    for (int ks = 0; ks < 8; ks++) {
        qa[ks][0] = Ps[(mrow+g)*APAD   + 8*ks + t];
        qa[ks][1] = Ps[(mrow+g+8)*APAD + 8*ks + t];
        qa[ks][2] = Ps[(mrow+g)*APAD   + 8*ks + t + 4];
        qa[ks][3] = Ps[(mrow+g+8)*APAD + 8*ks + t + 4];
    }
    __syncthreads();

    float m0 = -1e30f, m1 = -1e30f, l0 = 0.f, l1 = 0.f;
    float co[8][4];
    #pragma unroll
    for (int dj = 0; dj < 8; dj++)
        #pragma unroll
        for (int r = 0; r < 4; r++) co[dj][r] = 0.f;

    const int* mrow_mask = mask + b*SS;

    for (int kt = 0; kt < SS/64; kt++) {
        // load K,V tiles (64x64 each)
        for (int i = tid; i < 64*16; i += 128) {
            const int r = i >> 4, c = (i & 15) * 4;
            float4 kv = *(const float4*)(Kg + (size_t)(kt*64 + r)*HDD + c);
            float4 vv = *(const float4*)(Vg + (size_t)(kt*64 + r)*HDD + c);
            Ks[r*APAD + c+0] = f2tf32(kv.x); Ks[r*APAD + c+1] = f2tf32(kv.y);
            Ks[r*APAD + c+2] = f2tf32(kv.z); Ks[r*APAD + c+3] = f2tf32(kv.w);
            Vs[r*APAD + c+0] = f2tf32(vv.x); Vs[r*APAD + c+1] = f2tf32(vv.y);
            Vs[r*APAD + c+2] = f2tf32(vv.z); Vs[r*APAD + c+3] = f2tf32(vv.w);
        }
        __syncthreads();

        // scores = Q @ K^T   (warp's 16 rows x 64 keys)
        float sc[8][4];
        #pragma unroll
        for (int j = 0; j < 8; j++)
            #pragma unroll
            for (int r = 0; r < 4; r++) sc[j][r] = 0.f;

        #pragma unroll
        for (int ks = 0; ks < 8; ks++) {
            #pragma unroll
            for (int j = 0; j < 8; j++) {
                const int rn = (8*j + g) * APAD + 8*ks + t;
                mma_tf32(sc[j], qa[ks], Ks[rn], Ks[rn + 4]);
            }
        }

        // scale + mask
        #pragma unroll
        for (int j = 0; j < 8; j++) {
            const int key = kt*64 + 8*j + 2*t;
            const int mk0 = __ldg(mrow_mask + key);
            const int mk1 = __ldg(mrow_mask + key + 1);
            sc[j][0] = mk0 ? sc[j][0]*0.125f : -1e9f;
            sc[j][1] = mk1 ? sc[j][1]*0.125f : -1e9f;
            sc[j][2] = mk0 ? sc[j][2]*0.125f : -1e9f;
            sc[j][3] = mk1 ? sc[j][3]*0.125f : -1e9f;
        }

        // online softmax (lane owns rows g and g+8, 16 cols each)
        float mt0 = -1e30f, mt1 = -1e30f;
        #pragma unroll
        for (int j = 0; j < 8; j++) {
            mt0 = fmaxf(mt0, fmaxf(sc[j][0], sc[j][1]));
            mt1 = fmaxf(mt1, fmaxf(sc[j][2], sc[j][3]));
        }
        #pragma unroll
        for (int off = 1; off < 4; off <<= 1) {
            mt0 = fmaxf(mt0, __shfl_xor_sync(0xffffffffu, mt0, off));
            mt1 = fmaxf(mt1, __shfl_xor_sync(0xffffffffu, mt1, off));
        }
        const float mn0 = fmaxf(m0, mt0), mn1 = fmaxf(m1, mt1);
        const float cr0 = __expf(m0 - mn0), cr1 = __expf(m1 - mn1);
        m0 = mn0; m1 = mn1;

        float rs0 = 0.f, rs1 = 0.f;
        #pragma unroll
        for (int j = 0; j < 8; j++) {
            sc[j][0] = __expf(sc[j][0] - mn0);
            sc[j][1] = __expf(sc[j][1] - mn0);
            sc[j][2] = __expf(sc[j][2] - mn1);
            sc[j][3] = __expf(sc[j][3] - mn1);
            rs0 += sc[j][0] + sc[j][1];
            rs1 += sc[j][2] + sc[j][3];
        }
        #pragma unroll
        for (int off = 1; off < 4; off <<= 1) {
            rs0 += __shfl_xor_sync(0xffffffffu, rs0, off);
            rs1 += __shfl_xor_sync(0xffffffffu, rs1, off);
        }
        l0 = l0*cr0 + rs0;
        l1 = l1*cr1 + rs1;

        #pragma unroll
        for (int dj = 0; dj < 8; dj++) {
            co[dj][0] *= cr0; co[dj][1] *= cr0;
            co[dj][2] *= cr1; co[dj][3] *= cr1;
        }

        // write P (tf32) to Ps — consumed only by this warp
        #pragma unroll
        for (int j = 0; j < 8; j++) {
            const int c = 8*j + 2*t;
            Ps[(mrow+g)*APAD   + c]     = f2tf32(sc[j][0]);
            Ps[(mrow+g)*APAD   + c + 1] = f2tf32(sc[j][1]);
            Ps[(mrow+g+8)*APAD + c]     = f2tf32(sc[j][2]);
            Ps[(mrow+g+8)*APAD + c + 1] = f2tf32(sc[j][3]);
        }
        __syncwarp();

        // out += P @ V
        #pragma unroll
        for (int kk = 0; kk < 8; kk++) {
            unsigned pa[4];
            pa[0] = Ps[(mrow+g)*APAD   + 8*kk + t];
            pa[1] = Ps[(mrow+g+8)*APAD + 8*kk + t];
            pa[2] = Ps[(mrow+g)*APAD   + 8*kk + t + 4];
            pa[3] = Ps[(mrow+g+8)*APAD + 8*kk + t + 4];
            #pragma unroll
            for (int dj = 0; dj < 8; dj++) {
                const unsigned b0 = Vs[(8*kk + t)*APAD     + 8*dj + g];
                const unsigned b1 = Vs[(8*kk + t + 4)*APAD + 8*dj + g];
                mma_tf32(co[dj], pa, b0, b1);
            }
        }
        __syncthreads();
    }

    // epilogue: normalize, write [B,S,D]
    const float inv0 = 1.f / l0, inv1 = 1.f / l1;
    const int s0 = qt*64 + mrow + g;
    #pragma unroll
    for (int dj = 0; dj < 8; dj++) {
        const int col = h*HDD + 8*dj + 2*t;
        float2 v0 = make_float2(co[dj][0]*inv0, co[dj][1]*inv0);
        float2 v1 = make_float2(co[dj][2]*inv1, co[dj][3]*inv1);
        *(float2*)(O + ((size_t)(b*SS + s0))*DDIM + col)     = v0;
        *(float2*)(O + ((size_t)(b*SS + s0 + 8))*DDIM + col) = v1;
    }
}

// ---------------------------------------------------------------------------
extern "C" void kernel_launch(void* const* d_in, const int* in_sizes, int n_in,
                              void* d_out, int out_size)
{
    const float* x    = (const float*)d_in[0];
    const int*   mask = (const int*)  d_in[1];
    const float* Wq   = (const float*)d_in[2];
    const float* bq   = (const float*)d_in[3];
    const float* Wk   = (const float*)d_in[4];
    const float* bk   = (const float*)d_in[5];
    const float* Wv   = (const float*)d_in[6];
    const float* bv   = (const float*)d_in[7];
    const float* Wo   = (const float*)d_in[8];
    const float* bo   = (const float*)d_in[9];
    float* out = (float*)d_out;

    float *q, *k, *v, *att;
    cudaGetSymbolAddress((void**)&q,   g_q);
    cudaGetSymbolAddress((void**)&k,   g_k);
    cudaGetSymbolAddress((void**)&v,   g_v);
    cudaGetSymbolAddress((void**)&att, g_att);

    const int attn_smem = 3 * 64 * APAD * 4;   // 52224 B
    cudaFuncSetAttribute(attention_tf32_kernel,
                         cudaFuncAttributeMaxDynamicSharedMemorySize, attn_smem);

    const dim3 gGemm(DDIM/128, (BB*SS)/128);   // (8, 32)
    gemm_tf32_kernel<true><<<gGemm, 256>>>(x, Wq, bq, q);
    gemm_tf32_kernel<true><<<gGemm, 256>>>(x, Wk, bk, k);
    gemm_tf32_kernel<true><<<gGemm, 256>>>(x, Wv, bv, v);

    const dim3 gAttn(SS/64, HH, BB);           // (32, 16, 2)
    attention_tf32_kernel<<<gAttn, 128, attn_smem>>>(mask, att);

    gemm_tf32_kernel<false><<<gGemm, 256>>>(att, Wo, bo, out);
}

// round 10
// speedup vs baseline: 3.5264x; 1.0236x over previous
#include <cuda_runtime.h>

#define BB   2
#define SS   2048
#define DDIM 1024
#define HH   16
#define HDD  64

// Scratch (allocation-free rule: __device__ globals)
__device__ float g_q[(size_t)BB*HH*SS*HDD];   // [B,H,S,HD]
__device__ float g_k[(size_t)BB*HH*SS*HDD];
__device__ float g_v[(size_t)BB*HH*SS*HDD];
__device__ float g_att[(size_t)BB*SS*DDIM];   // [B,S,D]

// ---------------------------------------------------------------------------
__device__ __forceinline__ unsigned f2tf32(float x) {
    unsigned r;
    asm("cvt.rna.tf32.f32 %0, %1;" : "=r"(r) : "f"(x));
    return r;
}

__device__ __forceinline__ void mma_tf32(float* c, const unsigned* a,
                                         unsigned b0, unsigned b1) {
    asm volatile(
        "mma.sync.aligned.m16n8k8.row.col.f32.tf32.tf32.f32 "
        "{%0,%1,%2,%3}, {%4,%5,%6,%7}, {%8,%9}, {%0,%1,%2,%3};\n"
        : "+f"(c[0]), "+f"(c[1]), "+f"(c[2]), "+f"(c[3])
        : "r"(a[0]), "r"(a[1]), "r"(a[2]), "r"(a[3]), "r"(b0), "r"(b1));
}

// Packed-pair layouts: fragment pair (col t, col t+4) stored adjacent -> LDS.64.
// Col-group pack (K / Q / P / GEMM tiles): kk = col>>3, u = col&7.
//   word = kk*ROWS*8 + row*8 + 2*((u&3) ^ (kk&3)) + (u>>2)
// Row-group pack (V): kk = row>>3, u = row&7.
//   word = kk*512 + col*8 + 2*((u&3) ^ (kk&3) ^ ((col>>2)&3)) + (u>>2)

// ---------------------------------------------------------------------------
// TF32 GEMM: C[M,N] = X[M,K] @ W[N,K]^T + bias,  M=4096, N=K=1024.
// Block 256 thr (8 warps), tile 128x128, k-slab 16, double-buffered packed smem.
// ---------------------------------------------------------------------------
__device__ __forceinline__ void g_stpack(unsigned* buf, int row, int col, unsigned v) {
    const int kk = col >> 3, u = col & 7;
    buf[kk*1024 + row*8 + 2*((u&3) ^ kk) + (u>>2)] = v;
}

template<bool HEAD_MAJOR>
__global__ void __launch_bounds__(256, 2) gemm_tf32_kernel(
    const float* __restrict__ X, const float* __restrict__ W,
    const float* __restrict__ bias, float* __restrict__ C)
{
    __shared__ __align__(16) unsigned As[2][2048];   // [kk(2)][row(128)][8]
    __shared__ __align__(16) unsigned Bs[2][2048];

    const int tid  = threadIdx.x;
    const int warp = tid >> 5;
    const int lane = tid & 31;
    const int g    = lane >> 2;
    const int t    = lane & 3;
    const int wm   = (warp >> 2) * 64;
    const int wn   = (warp & 3) * 32;
    const int m0   = blockIdx.y * 128;
    const int n0   = blockIdx.x * 128;

    const int lr = tid >> 2;           // 0..63
    const int lc = (tid & 3) * 4;      // 0,4,8,12

    float acc[4][4][4];
    #pragma unroll
    for (int mi = 0; mi < 4; mi++)
        #pragma unroll
        for (int nj = 0; nj < 4; nj++)
            #pragma unroll
            for (int r = 0; r < 4; r++) acc[mi][nj][r] = 0.f;

    float4 ax0 = *(const float4*)(X + (size_t)(m0 + lr)      * DDIM + lc);
    float4 ax1 = *(const float4*)(X + (size_t)(m0 + lr + 64) * DDIM + lc);
    float4 bx0 = *(const float4*)(W + (size_t)(n0 + lr)      * DDIM + lc);
    float4 bx1 = *(const float4*)(W + (size_t)(n0 + lr + 64) * DDIM + lc);
    {
        unsigned* a = As[0]; unsigned* b = Bs[0];
        g_stpack(a, lr, lc+0, f2tf32(ax0.x)); g_stpack(a, lr, lc+1, f2tf32(ax0.y));
        g_stpack(a, lr, lc+2, f2tf32(ax0.z)); g_stpack(a, lr, lc+3, f2tf32(ax0.w));
        g_stpack(a, lr+64, lc+0, f2tf32(ax1.x)); g_stpack(a, lr+64, lc+1, f2tf32(ax1.y));
        g_stpack(a, lr+64, lc+2, f2tf32(ax1.z)); g_stpack(a, lr+64, lc+3, f2tf32(ax1.w));
        g_stpack(b, lr, lc+0, f2tf32(bx0.x)); g_stpack(b, lr, lc+1, f2tf32(bx0.y));
        g_stpack(b, lr, lc+2, f2tf32(bx0.z)); g_stpack(b, lr, lc+3, f2tf32(bx0.w));
        g_stpack(b, lr+64, lc+0, f2tf32(bx1.x)); g_stpack(b, lr+64, lc+1, f2tf32(bx1.y));
        g_stpack(b, lr+64, lc+2, f2tf32(bx1.z)); g_stpack(b, lr+64, lc+3, f2tf32(bx1.w));
    }
    __syncthreads();

    int buf = 0;
    for (int ks = 0; ks < DDIM/16; ks++) {
        if (ks < DDIM/16 - 1) {
            const int kn = (ks + 1) * 16;
            ax0 = *(const float4*)(X + (size_t)(m0 + lr)      * DDIM + kn + lc);
            ax1 = *(const float4*)(X + (size_t)(m0 + lr + 64) * DDIM + kn + lc);
            bx0 = *(const float4*)(W + (size_t)(n0 + lr)      * DDIM + kn + lc);
            bx1 = *(const float4*)(W + (size_t)(n0 + lr + 64) * DDIM + kn + lc);
        }

        const unsigned* a_s = As[buf];
        const unsigned* b_s = Bs[buf];
        #pragma unroll
        for (int kk = 0; kk < 2; kk++) {
            unsigned afr[4][4];
            #pragma unroll
            for (int mi = 0; mi < 4; mi++) {
                const int r = wm + 16*mi + g;
                uint2 a0 = *(const uint2*)&a_s[kk*1024 + r*8     + 2*(t^kk)];
                uint2 a1 = *(const uint2*)&a_s[kk*1024 + (r+8)*8 + 2*(t^kk)];
                afr[mi][0] = a0.x; afr[mi][1] = a1.x;
                afr[mi][2] = a0.y; afr[mi][3] = a1.y;
            }
            #pragma unroll
            for (int nj = 0; nj < 4; nj++) {
                const int rn = wn + 8*nj + g;
                uint2 bfr = *(const uint2*)&b_s[kk*1024 + rn*8 + 2*(t^kk)];
                #pragma unroll
                for (int mi = 0; mi < 4; mi++)
                    mma_tf32(acc[mi][nj], afr[mi], bfr.x, bfr.y);
            }
        }

        if (ks < DDIM/16 - 1) {
            unsigned* a = As[buf ^ 1]; unsigned* b = Bs[buf ^ 1];
            g_stpack(a, lr, lc+0, f2tf32(ax0.x)); g_stpack(a, lr, lc+1, f2tf32(ax0.y));
            g_stpack(a, lr, lc+2, f2tf32(ax0.z)); g_stpack(a, lr, lc+3, f2tf32(ax0.w));
            g_stpack(a, lr+64, lc+0, f2tf32(ax1.x)); g_stpack(a, lr+64, lc+1, f2tf32(ax1.y));
            g_stpack(a, lr+64, lc+2, f2tf32(ax1.z)); g_stpack(a, lr+64, lc+3, f2tf32(ax1.w));
            g_stpack(b, lr, lc+0, f2tf32(bx0.x)); g_stpack(b, lr, lc+1, f2tf32(bx0.y));
            g_stpack(b, lr, lc+2, f2tf32(bx0.z)); g_stpack(b, lr, lc+3, f2tf32(bx0.w));
            g_stpack(b, lr+64, lc+0, f2tf32(bx1.x)); g_stpack(b, lr+64, lc+1, f2tf32(bx1.y));
            g_stpack(b, lr+64, lc+2, f2tf32(bx1.z)); g_stpack(b, lr+64, lc+3, f2tf32(bx1.w));
        }
        __syncthreads();
        buf ^= 1;
    }

    #pragma unroll
    for (int mi = 0; mi < 4; mi++) {
        const int mA = m0 + wm + 16*mi + g;
        #pragma unroll
        for (int nj = 0; nj < 4; nj++) {
            const int n = n0 + wn + 8*nj + 2*t;
            const float b0 = bias[n], b1 = bias[n+1];
            float2 v0 = make_float2(acc[mi][nj][0] + b0, acc[mi][nj][1] + b1);
            float2 v1 = make_float2(acc[mi][nj][2] + b0, acc[mi][nj][3] + b1);
            if (HEAD_MAJOR) {
                const int h = n >> 6, d = n & 63;
                const int bb0 = mA >> 11, s0 = mA & 2047;
                *(float2*)(C + (((size_t)(bb0*HH + h))*SS + s0)*HDD + d) = v0;
                const int mB = mA + 8;
                const int bb1 = mB >> 11, s1 = mB & 2047;
                *(float2*)(C + (((size_t)(bb1*HH + h))*SS + s1)*HDD + d) = v1;
            } else {
                *(float2*)(C + (size_t)mA*DDIM + n)     = v0;
                *(float2*)(C + (size_t)(mA+8)*DDIM + n) = v1;
            }
        }
    }
}

// ---------------------------------------------------------------------------
// TF32 flash attention v2. Block = 256 thr (8 warps), Q tile = 128 rows
// (16 rows/warp), key tile 64. Dense packed smem: K 16KB + V 16KB + P/Q 32KB.
// ---------------------------------------------------------------------------
__device__ __forceinline__ void k_stpack(unsigned* buf, int row, int col, unsigned v) {
    const int kk = col >> 3, u = col & 7;          // col-group pack, 64 rows
    buf[kk*512 + row*8 + 2*((u&3) ^ (kk&3)) + (u>>2)] = v;
}
__device__ __forceinline__ void v_stpack(unsigned* buf, int row, int col, unsigned v) {
    const int kk = row >> 3, u = row & 7;          // row-group pack
    buf[kk*512 + col*8 + 2*((u&3) ^ (kk&3) ^ ((col>>2)&3)) + (u>>2)] = v;
}
__device__ __forceinline__ void p_stpack(unsigned* buf, int row, int col, unsigned v) {
    const int kk = col >> 3, u = col & 7;          // col-group pack, 128 rows
    buf[kk*1024 + row*8 + 2*((u&3) ^ (kk&3)) + (u>>2)] = v;
}

__global__ void __launch_bounds__(256, 2) attention_tf32_kernel(
    const int* __restrict__ mask, float* __restrict__ O)
{
    extern __shared__ __align__(16) unsigned sm[];
    unsigned* Kp = sm;            // 4096 words
    unsigned* Vp = sm + 4096;     // 4096 words
    unsigned* Pp = sm + 8192;     // 8192 words (Q staging, then P)

    const int qt = blockIdx.x;
    const int h  = blockIdx.y;
    const int b  = blockIdx.z;

    const float* __restrict__ Qg = g_q + ((size_t)(b*HH + h))*SS*HDD + (size_t)qt*128*HDD;
    const float* __restrict__ Kg = g_k + ((size_t)(b*HH + h))*SS*HDD;
    const float* __restrict__ Vg = g_v + ((size_t)(b*HH + h))*SS*HDD;

    const int tid  = threadIdx.x;
    const int warp = tid >> 5;
    const int lane = tid & 31;
    const int g    = lane >> 2;
    const int t    = lane & 3;
    const int mrow = warp * 16;

    // stage Q (128x64) packed into Pp
    for (int i = tid; i < 128*16; i += 256) {
        const int r = i >> 4, c = (i & 15) * 4;
        float4 v = *(const float4*)(Qg + (size_t)r*HDD + c);
        p_stpack(Pp, r, c+0, f2tf32(v.x)); p_stpack(Pp, r, c+1, f2tf32(v.y));
        p_stpack(Pp, r, c+2, f2tf32(v.z)); p_stpack(Pp, r, c+3, f2tf32(v.w));
    }
    __syncthreads();

    unsigned qa[8][4];
    #pragma unroll
    for (int ks = 0; ks < 8; ks++) {
        uint2 q0 = *(const uint2*)&Pp[ks*1024 + (mrow+g)*8   + 2*(t^(ks&3))];
        uint2 q1 = *(const uint2*)&Pp[ks*1024 + (mrow+g+8)*8 + 2*(t^(ks&3))];
        qa[ks][0] = q0.x; qa[ks][1] = q1.x; qa[ks][2] = q0.y; qa[ks][3] = q1.y;
    }

    float m0 = -1e30f, m1 = -1e30f, l0 = 0.f, l1 = 0.f;
    float co[8][4];
    #pragma unroll
    for (int dj = 0; dj < 8; dj++)
        #pragma unroll
        for (int r = 0; r < 4; r++) co[dj][r] = 0.f;

    const int* mrow_mask = mask + b*SS;

    for (int kt = 0; kt < SS/64; kt++) {
        __syncthreads();   // all warps done reading previous K/V (and qa on iter 0)
        for (int i = tid; i < 64*16; i += 256) {
            const int r = i >> 4, c = (i & 15) * 4;
            float4 kv = *(const float4*)(Kg + (size_t)(kt*64 + r)*HDD + c);
            float4 vv = *(const float4*)(Vg + (size_t)(kt*64 + r)*HDD + c);
            k_stpack(Kp, r, c+0, f2tf32(kv.x)); k_stpack(Kp, r, c+1, f2tf32(kv.y));
            k_stpack(Kp, r, c+2, f2tf32(kv.z)); k_stpack(Kp, r, c+3, f2tf32(kv.w));
            v_stpack(Vp, r, c+0, f2tf32(vv.x)); v_stpack(Vp, r, c+1, f2tf32(vv.y));
            v_stpack(Vp, r, c+2, f2tf32(vv.z)); v_stpack(Vp, r, c+3, f2tf32(vv.w));
        }
        __syncthreads();

        // scores = Q @ K^T   (warp's 16 rows x 64 keys)
        float sc[8][4];
        #pragma unroll
        for (int j = 0; j < 8; j++)
            #pragma unroll
            for (int r = 0; r < 4; r++) sc[j][r] = 0.f;

        #pragma unroll
        for (int ks = 0; ks < 8; ks++) {
            #pragma unroll
            for (int j = 0; j < 8; j++) {
                uint2 bf = *(const uint2*)&Kp[ks*512 + (8*j+g)*8 + 2*(t^(ks&3))];
                mma_tf32(sc[j], qa[ks], bf.x, bf.y);
            }
        }

        // scale + mask
        #pragma unroll
        for (int j = 0; j < 8; j++) {
            const int key = kt*64 + 8*j + 2*t;
            const int mk0 = __ldg(mrow_mask + key);
            const int mk1 = __ldg(mrow_mask + key + 1);
            sc[j][0] = mk0 ? sc[j][0]*0.125f : -1e9f;
            sc[j][1] = mk1 ? sc[j][1]*0.125f : -1e9f;
            sc[j][2] = mk0 ? sc[j][2]*0.125f : -1e9f;
            sc[j][3] = mk1 ? sc[j][3]*0.125f : -1e9f;
        }

        // online softmax (lane owns rows mrow+g and mrow+g+8)
        float mt0 = -1e30f, mt1 = -1e30f;
        #pragma unroll
        for (int j = 0; j < 8; j++) {
            mt0 = fmaxf(mt0, fmaxf(sc[j][0], sc[j][1]));
            mt1 = fmaxf(mt1, fmaxf(sc[j][2], sc[j][3]));
        }
        #pragma unroll
        for (int off = 1; off < 4; off <<= 1) {
            mt0 = fmaxf(mt0, __shfl_xor_sync(0xffffffffu, mt0, off));
            mt1 = fmaxf(mt1, __shfl_xor_sync(0xffffffffu, mt1, off));
        }
        const float mn0 = fmaxf(m0, mt0), mn1 = fmaxf(m1, mt1);
        const float cr0 = __expf(m0 - mn0), cr1 = __expf(m1 - mn1);
        m0 = mn0; m1 = mn1;

        float rs0 = 0.f, rs1 = 0.f;
        #pragma unroll
        for (int j = 0; j < 8; j++) {
            sc[j][0] = __expf(sc[j][0] - mn0);
            sc[j][1] = __expf(sc[j][1] - mn0);
            sc[j][2] = __expf(sc[j][2] - mn1);
            sc[j][3] = __expf(sc[j][3] - mn1);
            rs0 += sc[j][0] + sc[j][1];
            rs1 += sc[j][2] + sc[j][3];
        }
        #pragma unroll
        for (int off = 1; off < 4; off <<= 1) {
            rs0 += __shfl_xor_sync(0xffffffffu, rs0, off);
            rs1 += __shfl_xor_sync(0xffffffffu, rs1, off);
        }
        l0 = l0*cr0 + rs0;
        l1 = l1*cr1 + rs1;

        #pragma unroll
        for (int dj = 0; dj < 8; dj++) {
            co[dj][0] *= cr0; co[dj][1] *= cr0;
            co[dj][2] *= cr1; co[dj][3] *= cr1;
        }

        // write P packed (this warp's private rows) — conflict-free
        #pragma unroll
        for (int j = 0; j < 8; j++) {
            p_stpack(Pp, mrow+g,   8*j + 2*t,     f2tf32(sc[j][0]));
            p_stpack(Pp, mrow+g,   8*j + 2*t + 1, f2tf32(sc[j][1]));
            p_stpack(Pp, mrow+g+8, 8*j + 2*t,     f2tf32(sc[j][2]));
            p_stpack(Pp, mrow+g+8, 8*j + 2*t + 1, f2tf32(sc[j][3]));
        }
        __syncwarp();

        // out += P @ V
        #pragma unroll
        for (int kk = 0; kk < 8; kk++) {
            uint2 p0 = *(const uint2*)&Pp[kk*1024 + (mrow+g)*8   + 2*(t^(kk&3))];
            uint2 p1 = *(const uint2*)&Pp[kk*1024 + (mrow+g+8)*8 + 2*(t^(kk&3))];
            unsigned pa[4] = {p0.x, p1.x, p0.y, p1.y};
            #pragma unroll
            for (int dj = 0; dj < 8; dj++) {
                const int c = 8*dj + g;
                uint2 bf = *(const uint2*)&Vp[kk*512 + c*8 +
                                              2*(t ^ (kk&3) ^ ((c>>2)&3))];
                mma_tf32(co[dj], pa, bf.x, bf.y);
            }
        }
    }

    // epilogue: normalize, write [B,S,D]
    const float inv0 = 1.f / l0, inv1 = 1.f / l1;
    const int s0 = qt*128 + mrow + g;
    #pragma unroll
    for (int dj = 0; dj < 8; dj++) {
        const int col = h*HDD + 8*dj + 2*t;
        float2 v0 = make_float2(co[dj][0]*inv0, co[dj][1]*inv0);
        float2 v1 = make_float2(co[dj][2]*inv1, co[dj][3]*inv1);
        *(float2*)(O + ((size_t)(b*SS + s0))*DDIM + col)     = v0;
        *(float2*)(O + ((size_t)(b*SS + s0 + 8))*DDIM + col) = v1;
    }
}

// ---------------------------------------------------------------------------
extern "C" void kernel_launch(void* const* d_in, const int* in_sizes, int n_in,
                              void* d_out, int out_size)
{
    const float* x    = (const float*)d_in[0];
    const int*   mask = (const int*)  d_in[1];
    const float* Wq   = (const float*)d_in[2];
    const float* bq   = (const float*)d_in[3];
    const float* Wk   = (const float*)d_in[4];
    const float* bk   = (const float*)d_in[5];
    const float* Wv   = (const float*)d_in[6];
    const float* bv   = (const float*)d_in[7];
    const float* Wo   = (const float*)d_in[8];
    const float* bo   = (const float*)d_in[9];
    float* out = (float*)d_out;

    float *q, *k, *v, *att;
    cudaGetSymbolAddress((void**)&q,   g_q);
    cudaGetSymbolAddress((void**)&k,   g_k);
    cudaGetSymbolAddress((void**)&v,   g_v);
    cudaGetSymbolAddress((void**)&att, g_att);

    const int attn_smem = 16384 * 4;   // 65536 B (K 16K + V 16K + P/Q 32K)
    cudaFuncSetAttribute(attention_tf32_kernel,
                         cudaFuncAttributeMaxDynamicSharedMemorySize, attn_smem);

    const dim3 gGemm(DDIM/128, (BB*SS)/128);   // (8, 32)
    gemm_tf32_kernel<true><<<gGemm, 256>>>(x, Wq, bq, q);
    gemm_tf32_kernel<true><<<gGemm, 256>>>(x, Wk, bk, k);
    gemm_tf32_kernel<true><<<gGemm, 256>>>(x, Wv, bv, v);

    const dim3 gAttn(SS/128, HH, BB);          // (16, 16, 2)
    attention_tf32_kernel<<<gAttn, 256, attn_smem>>>(mask, att);

    gemm_tf32_kernel<false><<<gGemm, 256>>>(att, Wo, bo, out);
}

// round 11
// speedup vs baseline: 3.9785x; 1.1282x over previous
#include <cuda_runtime.h>

#define BB   2
#define SS   2048
#define DDIM 1024
#define HH   16
#define HDD  64

// Scratch (allocation-free rule: __device__ globals).
// g_q/g_k/g_v hold tf32-rounded values PRE-PACKED in the attention smem tile
// layout, so the attention kernel can cp.async them as linear 16B chunks.
__device__ float g_q[(size_t)BB*HH*SS*HDD];
__device__ float g_k[(size_t)BB*HH*SS*HDD];
__device__ float g_v[(size_t)BB*HH*SS*HDD];
__device__ float g_att[(size_t)BB*SS*DDIM];   // [B,S,D] fp32

// ---------------------------------------------------------------------------
__device__ __forceinline__ unsigned f2tf32(float x) {
    unsigned r;
    asm("cvt.rna.tf32.f32 %0, %1;" : "=r"(r) : "f"(x));
    return r;
}

__device__ __forceinline__ void mma_tf32(float* c, const unsigned* a,
                                         unsigned b0, unsigned b1) {
    asm volatile(
        "mma.sync.aligned.m16n8k8.row.col.f32.tf32.tf32.f32 "
        "{%0,%1,%2,%3}, {%4,%5,%6,%7}, {%8,%9}, {%0,%1,%2,%3};\n"
        : "+f"(c[0]), "+f"(c[1]), "+f"(c[2]), "+f"(c[3])
        : "r"(a[0]), "r"(a[1]), "r"(a[2]), "r"(a[3]), "r"(b0), "r"(b1));
}

__device__ __forceinline__ void cp16(unsigned smaddr, const void* g) {
    asm volatile("cp.async.ca.shared.global [%0], [%1], 16;"
                 :: "r"(smaddr), "l"(g));
}
__device__ __forceinline__ void cp_commit() {
    asm volatile("cp.async.commit_group;");
}
template<int N> __device__ __forceinline__ void cp_wait() {
    asm volatile("cp.async.wait_group %0;" :: "n"(N));
}

// Packed-pair tile layouts (word offsets within one [b,h] plane of SS*HDD):
// Q: 128-row tiles, col-group pack.  K: 64-row tiles, col-group pack.
// V: 64-row tiles, row-group pack.
__device__ __forceinline__ int qoff(int s, int d) {
    const int kk = d >> 3, u = d & 7;
    return (s >> 7)*8192 + kk*1024 + (s & 127)*8 + 2*((u&3) ^ (kk&3)) + (u>>2);
}
__device__ __forceinline__ int koff(int s, int d) {
    const int kk = d >> 3, u = d & 7;
    return (s >> 6)*4096 + kk*512 + (s & 63)*8 + 2*((u&3) ^ (kk&3)) + (u>>2);
}
__device__ __forceinline__ int voff(int s, int d) {
    const int r = s & 63, kk = r >> 3, u = r & 7;
    return (s >> 6)*4096 + kk*512 + d*8 + 2*((u&3) ^ (kk&3) ^ ((d>>2)&3)) + (u>>2);
}

// ---------------------------------------------------------------------------
// TF32 GEMM: C[M,N] = X[M,K] @ W[N,K]^T + bias,  M=4096, N=K=1024.
// MODE: 0 = plain fp32 [M,N] output; 1/2/3 = tf32-packed Q/K/V scatter.
// ---------------------------------------------------------------------------
__device__ __forceinline__ void g_stpack(unsigned* buf, int row, int col, unsigned v) {
    const int kk = col >> 3, u = col & 7;
    buf[kk*1024 + row*8 + 2*((u&3) ^ kk) + (u>>2)] = v;
}

template<int MODE>
__global__ void __launch_bounds__(256, 2) gemm_tf32_kernel(
    const float* __restrict__ X, const float* __restrict__ W,
    const float* __restrict__ bias, float* __restrict__ C)
{
    __shared__ __align__(16) unsigned As[2][2048];   // [kk(2)][row(128)][8]
    __shared__ __align__(16) unsigned Bs[2][2048];

    const int tid  = threadIdx.x;
    const int warp = tid >> 5;
    const int lane = tid & 31;
    const int g    = lane >> 2;
    const int t    = lane & 3;
    const int wm   = (warp >> 2) * 64;
    const int wn   = (warp & 3) * 32;
    const int m0   = blockIdx.y * 128;
    const int n0   = blockIdx.x * 128;

    const int lr = tid >> 2;           // 0..63
    const int lc = (tid & 3) * 4;      // 0,4,8,12

    float acc[4][4][4];
    #pragma unroll
    for (int mi = 0; mi < 4; mi++)
        #pragma unroll
        for (int nj = 0; nj < 4; nj++)
            #pragma unroll
            for (int r = 0; r < 4; r++) acc[mi][nj][r] = 0.f;

    float4 ax0 = *(const float4*)(X + (size_t)(m0 + lr)      * DDIM + lc);
    float4 ax1 = *(const float4*)(X + (size_t)(m0 + lr + 64) * DDIM + lc);
    float4 bx0 = *(const float4*)(W + (size_t)(n0 + lr)      * DDIM + lc);
    float4 bx1 = *(const float4*)(W + (size_t)(n0 + lr + 64) * DDIM + lc);
    {
        unsigned* a = As[0]; unsigned* b = Bs[0];
        g_stpack(a, lr, lc+0, f2tf32(ax0.x)); g_stpack(a, lr, lc+1, f2tf32(ax0.y));
        g_stpack(a, lr, lc+2, f2tf32(ax0.z)); g_stpack(a, lr, lc+3, f2tf32(ax0.w));
        g_stpack(a, lr+64, lc+0, f2tf32(ax1.x)); g_stpack(a, lr+64, lc+1, f2tf32(ax1.y));
        g_stpack(a, lr+64, lc+2, f2tf32(ax1.z)); g_stpack(a, lr+64, lc+3, f2tf32(ax1.w));
        g_stpack(b, lr, lc+0, f2tf32(bx0.x)); g_stpack(b, lr, lc+1, f2tf32(bx0.y));
        g_stpack(b, lr, lc+2, f2tf32(bx0.z)); g_stpack(b, lr, lc+3, f2tf32(bx0.w));
        g_stpack(b, lr+64, lc+0, f2tf32(bx1.x)); g_stpack(b, lr+64, lc+1, f2tf32(bx1.y));
        g_stpack(b, lr+64, lc+2, f2tf32(bx1.z)); g_stpack(b, lr+64, lc+3, f2tf32(bx1.w));
    }
    __syncthreads();

    int buf = 0;
    for (int ks = 0; ks < DDIM/16; ks++) {
        if (ks < DDIM/16 - 1) {
            const int kn = (ks + 1) * 16;
            ax0 = *(const float4*)(X + (size_t)(m0 + lr)      * DDIM + kn + lc);
            ax1 = *(const float4*)(X + (size_t)(m0 + lr + 64) * DDIM + kn + lc);
            bx0 = *(const float4*)(W + (size_t)(n0 + lr)      * DDIM + kn + lc);
            bx1 = *(const float4*)(W + (size_t)(n0 + lr + 64) * DDIM + kn + lc);
        }

        const unsigned* a_s = As[buf];
        const unsigned* b_s = Bs[buf];
        #pragma unroll
        for (int kk = 0; kk < 2; kk++) {
            unsigned afr[4][4];
            #pragma unroll
            for (int mi = 0; mi < 4; mi++) {
                const int r = wm + 16*mi + g;
                uint2 a0 = *(const uint2*)&a_s[kk*1024 + r*8     + 2*(t^kk)];
                uint2 a1 = *(const uint2*)&a_s[kk*1024 + (r+8)*8 + 2*(t^kk)];
                afr[mi][0] = a0.x; afr[mi][1] = a1.x;
                afr[mi][2] = a0.y; afr[mi][3] = a1.y;
            }
            #pragma unroll
            for (int nj = 0; nj < 4; nj++) {
                const int rn = wn + 8*nj + g;
                uint2 bfr = *(const uint2*)&b_s[kk*1024 + rn*8 + 2*(t^kk)];
                #pragma unroll
                for (int mi = 0; mi < 4; mi++)
                    mma_tf32(acc[mi][nj], afr[mi], bfr.x, bfr.y);
            }
        }

        if (ks < DDIM/16 - 1) {
            unsigned* a = As[buf ^ 1]; unsigned* b = Bs[buf ^ 1];
            g_stpack(a, lr, lc+0, f2tf32(ax0.x)); g_stpack(a, lr, lc+1, f2tf32(ax0.y));
            g_stpack(a, lr, lc+2, f2tf32(ax0.z)); g_stpack(a, lr, lc+3, f2tf32(ax0.w));
            g_stpack(a, lr+64, lc+0, f2tf32(ax1.x)); g_stpack(a, lr+64, lc+1, f2tf32(ax1.y));
            g_stpack(a, lr+64, lc+2, f2tf32(ax1.z)); g_stpack(a, lr+64, lc+3, f2tf32(ax1.w));
            g_stpack(b, lr, lc+0, f2tf32(bx0.x)); g_stpack(b, lr, lc+1, f2tf32(bx0.y));
            g_stpack(b, lr, lc+2, f2tf32(bx0.z)); g_stpack(b, lr, lc+3, f2tf32(bx0.w));
            g_stpack(b, lr+64, lc+0, f2tf32(bx1.x)); g_stpack(b, lr+64, lc+1, f2tf32(bx1.y));
            g_stpack(b, lr+64, lc+2, f2tf32(bx1.z)); g_stpack(b, lr+64, lc+3, f2tf32(bx1.w));
        }
        __syncthreads();
        buf ^= 1;
    }

    #pragma unroll
    for (int mi = 0; mi < 4; mi++) {
        const int mA = m0 + wm + 16*mi + g;
        #pragma unroll
        for (int nj = 0; nj < 4; nj++) {
            const int n = n0 + wn + 8*nj + 2*t;
            const float b0 = bias[n], b1 = bias[n+1];
            const float v00 = acc[mi][nj][0] + b0, v01 = acc[mi][nj][1] + b1;
            const float v10 = acc[mi][nj][2] + b0, v11 = acc[mi][nj][3] + b1;
            if (MODE == 0) {
                *(float2*)(C + (size_t)mA*DDIM + n)     = make_float2(v00, v01);
                *(float2*)(C + (size_t)(mA+8)*DDIM + n) = make_float2(v10, v11);
            } else {
                const int h = n >> 6, d = n & 63;
                unsigned* Cu = (unsigned*)C;
                #pragma unroll
                for (int rr = 0; rr < 2; rr++) {
                    const int m = mA + 8*rr;
                    const int bb = m >> 11, s = m & 2047;
                    const size_t plane = (size_t)(bb*HH + h) * (SS*HDD);
                    const float y0 = rr ? v10 : v00;
                    const float y1 = rr ? v11 : v01;
                    int o0, o1;
                    if (MODE == 1) { o0 = qoff(s, d); o1 = qoff(s, d+1); }
                    else if (MODE == 2) { o0 = koff(s, d); o1 = koff(s, d+1); }
                    else { o0 = voff(s, d); o1 = voff(s, d+1); }
                    Cu[plane + o0] = f2tf32(y0);
                    Cu[plane + o1] = f2tf32(y1);
                }
            }
        }
    }
}

// ---------------------------------------------------------------------------
// TF32 flash attention v3: cp.async double-buffered pre-packed K/V tiles.
// Block = 256 thr (8 warps), Q tile = 128 rows, key tile 64.
// Smem (words): Kd[2][4096] @0, Vd[2][4096] @8192, Pp[8192] @16384 = 96 KB.
// ---------------------------------------------------------------------------
__device__ __forceinline__ void p_stpack(unsigned* buf, int row, int col, unsigned v) {
    const int kk = col >> 3, u = col & 7;
    buf[kk*1024 + row*8 + 2*((u&3) ^ (kk&3)) + (u>>2)] = v;
}

__global__ void __launch_bounds__(256, 2) attention_tf32_kernel(
    const int* __restrict__ mask, float* __restrict__ O)
{
    extern __shared__ __align__(16) unsigned sm[];
    unsigned* Pp = sm + 16384;

    const int qt = blockIdx.x;
    const int h  = blockIdx.y;
    const int b  = blockIdx.z;

    const size_t plane = (size_t)(b*HH + h) * (SS*HDD);
    const float4* Qg4 = (const float4*)(g_q + plane) + qt*2048;
    const float4* Kg4 = (const float4*)(g_k + plane);
    const float4* Vg4 = (const float4*)(g_v + plane);

    const int tid  = threadIdx.x;
    const int warp = tid >> 5;
    const int lane = tid & 31;
    const int g    = lane >> 2;
    const int t    = lane & 3;
    const int mrow = warp * 16;

    const unsigned sbase = (unsigned)__cvta_generic_to_shared(sm);

    // Q tile (pre-packed, 8192 words) -> Pp via cp.async
    for (int i = tid; i < 2048; i += 256)
        cp16(sbase + 65536 + i*16, Qg4 + i);
    cp_commit();
    // K/V tile 0 -> buffer 0
    for (int i = tid; i < 1024; i += 256) {
        cp16(sbase +         i*16, Kg4 + i);
        cp16(sbase + 32768 + i*16, Vg4 + i);
    }
    cp_commit();
    cp_wait<1>();          // Q ready (tile0 may still be in flight)
    __syncthreads();

    unsigned qa[8][4];
    #pragma unroll
    for (int ks = 0; ks < 8; ks++) {
        uint2 q0 = *(const uint2*)&Pp[ks*1024 + (mrow+g)*8   + 2*(t^(ks&3))];
        uint2 q1 = *(const uint2*)&Pp[ks*1024 + (mrow+g+8)*8 + 2*(t^(ks&3))];
        qa[ks][0] = q0.x; qa[ks][1] = q1.x; qa[ks][2] = q0.y; qa[ks][3] = q1.y;
    }

    float m0 = -1e30f, m1 = -1e30f, l0 = 0.f, l1 = 0.f;
    float co[8][4];
    #pragma unroll
    for (int dj = 0; dj < 8; dj++)
        #pragma unroll
        for (int r = 0; r < 4; r++) co[dj][r] = 0.f;

    const int* mrow_mask = mask + b*SS;

    for (int kt = 0; kt < SS/64; kt++) {
        __syncthreads();   // all warps done with buffer (kt+1)&1 from tile kt-1
        if (kt + 1 < SS/64) {
            const int bs = (kt + 1) & 1;
            const float4* kc = Kg4 + (kt+1)*1024;
            const float4* vc = Vg4 + (kt+1)*1024;
            for (int i = tid; i < 1024; i += 256) {
                cp16(sbase +         bs*16384 + i*16, kc + i);
                cp16(sbase + 32768 + bs*16384 + i*16, vc + i);
            }
            cp_commit();
            cp_wait<1>();  // tile kt complete; kt+1 in flight
        } else {
            cp_wait<0>();
        }
        __syncthreads();

        const unsigned* Kp = sm +        (kt & 1)*4096;
        const unsigned* Vp = sm + 8192 + (kt & 1)*4096;

        // scores = Q @ K^T   (warp's 16 rows x 64 keys)
        float sc[8][4];
        #pragma unroll
        for (int j = 0; j < 8; j++)
            #pragma unroll
            for (int r = 0; r < 4; r++) sc[j][r] = 0.f;

        #pragma unroll
        for (int ks = 0; ks < 8; ks++) {
            #pragma unroll
            for (int j = 0; j < 8; j++) {
                uint2 bf = *(const uint2*)&Kp[ks*512 + (8*j+g)*8 + 2*(t^(ks&3))];
                mma_tf32(sc[j], qa[ks], bf.x, bf.y);
            }
        }

        // scale + mask
        #pragma unroll
        for (int j = 0; j < 8; j++) {
            const int key = kt*64 + 8*j + 2*t;
            const int mk0 = __ldg(mrow_mask + key);
            const int mk1 = __ldg(mrow_mask + key + 1);
            sc[j][0] = mk0 ? sc[j][0]*0.125f : -1e9f;
            sc[j][1] = mk1 ? sc[j][1]*0.125f : -1e9f;
            sc[j][2] = mk0 ? sc[j][2]*0.125f : -1e9f;
            sc[j][3] = mk1 ? sc[j][3]*0.125f : -1e9f;
        }

        // online softmax (lane owns rows mrow+g and mrow+g+8)
        float mt0 = -1e30f, mt1 = -1e30f;
        #pragma unroll
        for (int j = 0; j < 8; j++) {
            mt0 = fmaxf(mt0, fmaxf(sc[j][0], sc[j][1]));
            mt1 = fmaxf(mt1, fmaxf(sc[j][2], sc[j][3]));
        }
        #pragma unroll
        for (int off = 1; off < 4; off <<= 1) {
            mt0 = fmaxf(mt0, __shfl_xor_sync(0xffffffffu, mt0, off));
            mt1 = fmaxf(mt1, __shfl_xor_sync(0xffffffffu, mt1, off));
        }
        const float mn0 = fmaxf(m0, mt0), mn1 = fmaxf(m1, mt1);
        const float cr0 = __expf(m0 - mn0), cr1 = __expf(m1 - mn1);
        m0 = mn0; m1 = mn1;

        float rs0 = 0.f, rs1 = 0.f;
        #pragma unroll
        for (int j = 0; j < 8; j++) {
            sc[j][0] = __expf(sc[j][0] - mn0);
            sc[j][1] = __expf(sc[j][1] - mn0);
            sc[j][2] = __expf(sc[j][2] - mn1);
            sc[j][3] = __expf(sc[j][3] - mn1);
            rs0 += sc[j][0] + sc[j][1];
            rs1 += sc[j][2] + sc[j][3];
        }
        #pragma unroll
        for (int off = 1; off < 4; off <<= 1) {
            rs0 += __shfl_xor_sync(0xffffffffu, rs0, off);
            rs1 += __shfl_xor_sync(0xffffffffu, rs1, off);
        }
        l0 = l0*cr0 + rs0;
        l1 = l1*cr1 + rs1;

        #pragma unroll
        for (int dj = 0; dj < 8; dj++) {
            co[dj][0] *= cr0; co[dj][1] *= cr0;
            co[dj][2] *= cr1; co[dj][3] *= cr1;
        }

        // write P packed (warp-private rows)
        #pragma unroll
        for (int j = 0; j < 8; j++) {
            p_stpack(Pp, mrow+g,   8*j + 2*t,     f2tf32(sc[j][0]));
            p_stpack(Pp, mrow+g,   8*j + 2*t + 1, f2tf32(sc[j][1]));
            p_stpack(Pp, mrow+g+8, 8*j + 2*t,     f2tf32(sc[j][2]));
            p_stpack(Pp, mrow+g+8, 8*j + 2*t + 1, f2tf32(sc[j][3]));
        }
        __syncwarp();

        // out += P @ V
        #pragma unroll
        for (int kk = 0; kk < 8; kk++) {
            uint2 p0 = *(const uint2*)&Pp[kk*1024 + (mrow+g)*8   + 2*(t^(kk&3))];
            uint2 p1 = *(const uint2*)&Pp[kk*1024 + (mrow+g+8)*8 + 2*(t^(kk&3))];
            unsigned pa[4] = {p0.x, p1.x, p0.y, p1.y};
            #pragma unroll
            for (int dj = 0; dj < 8; dj++) {
                const int c = 8*dj + g;
                uint2 bf = *(const uint2*)&Vp[kk*512 + c*8 +
                                              2*(t ^ (kk&3) ^ ((c>>2)&3))];
                mma_tf32(co[dj], pa, bf.x, bf.y);
            }
        }
    }

    // epilogue: normalize, write [B,S,D]
    const float inv0 = 1.f / l0, inv1 = 1.f / l1;
    const int s0 = qt*128 + mrow + g;
    #pragma unroll
    for (int dj = 0; dj < 8; dj++) {
        const int col = h*HDD + 8*dj + 2*t;
        float2 v0 = make_float2(co[dj][0]*inv0, co[dj][1]*inv0);
        float2 v1 = make_float2(co[dj][2]*inv1, co[dj][3]*inv1);
        *(float2*)(O + ((size_t)(b*SS + s0))*DDIM + col)     = v0;
        *(float2*)(O + ((size_t)(b*SS + s0 + 8))*DDIM + col) = v1;
    }
}

// ---------------------------------------------------------------------------
extern "C" void kernel_launch(void* const* d_in, const int* in_sizes, int n_in,
                              void* d_out, int out_size)
{
    const float* x    = (const float*)d_in[0];
    const int*   mask = (const int*)  d_in[1];
    const float* Wq   = (const float*)d_in[2];
    const float* bq   = (const float*)d_in[3];
    const float* Wk   = (const float*)d_in[4];
    const float* bk   = (const float*)d_in[5];
    const float* Wv   = (const float*)d_in[6];
    const float* bv   = (const float*)d_in[7];
    const float* Wo   = (const float*)d_in[8];
    const float* bo   = (const float*)d_in[9];
    float* out = (float*)d_out;

    float *q, *k, *v, *att;
    cudaGetSymbolAddress((void**)&q,   g_q);
    cudaGetSymbolAddress((void**)&k,   g_k);
    cudaGetSymbolAddress((void**)&v,   g_v);
    cudaGetSymbolAddress((void**)&att, g_att);

    const int attn_smem = 24576 * 4;   // 98304 B
    cudaFuncSetAttribute(attention_tf32_kernel,
                         cudaFuncAttributeMaxDynamicSharedMemorySize, attn_smem);

    const dim3 gGemm(DDIM/128, (BB*SS)/128);   // (8, 32)
    gemm_tf32_kernel<1><<<gGemm, 256>>>(x, Wq, bq, q);
    gemm_tf32_kernel<2><<<gGemm, 256>>>(x, Wk, bk, k);
    gemm_tf32_kernel<3><<<gGemm, 256>>>(x, Wv, bv, v);

    const dim3 gAttn(SS/128, HH, BB);          // (16, 16, 2)
    attention_tf32_kernel<<<gAttn, 256, attn_smem>>>(mask, att);

    gemm_tf32_kernel<0><<<gGemm, 256>>>(att, Wo, bo, out);
}